// round 9
// baseline (speedup 1.0000x reference)
#include <cuda_runtime.h>
#include <cfloat>

// N=8192 tokens, K=4096, D=1024.
//   idx[n] = argmax_k x[n,k]  (first-occurrence tie-break)
//   out[n,d] = W[d, idx[n]]
//
// K1: float4 transpose W [D,K] -> g_Wt [K,D], 512 blocks x 2 tiles so it
//     occupies only ~half the SM slots — PDL lets K2's argmax stream run
//     concurrently on the remaining slots.
// K2: fused per-token argmax + row gather (PDL consumer): argmax phase reads
//     only x (overlaps K1), then cudaGridDependencySynchronize() gates the
//     g_Wt gather on K1 completion + flush.

#define NTOK 8192
#define KDIM 4096
#define DDIM 1024
#define TP_TILE 64
#define TP_NTILES ((KDIM / TP_TILE) * (DDIM / TP_TILE))   // 1024
#define TP_PER_BLOCK 2
#define TP_BLOCKS (TP_NTILES / TP_PER_BLOCK)              // 512

__device__ float g_Wt[(size_t)KDIM * DDIM];   // 16 MB scratch

// ---------------- K1: transpose, 2 tiles per block ----------------
__global__ void __launch_bounds__(256) transpose_kernel(const float* __restrict__ W)
{
#if __CUDA_ARCH__ >= 900
    cudaTriggerProgrammaticLaunchCompletion();   // let K2 co-schedule
#endif
    __shared__ float t[TP_TILE][TP_TILE + 1];
    const int tid = threadIdx.x;
    const int tx  = tid & 15;    // float4 lane along fast dim
    const int ty  = tid >> 4;    // row 0..15

    #pragma unroll
    for (int q = 0; q < TP_PER_BLOCK; ++q) {
        const int tile = blockIdx.x * TP_PER_BLOCK + q;
        const int k0 = (tile % (KDIM / TP_TILE)) * TP_TILE;
        const int d0 = (tile / (KDIM / TP_TILE)) * TP_TILE;

        #pragma unroll
        for (int i = 0; i < 4; ++i) {
            int r = ty + 16 * i;
            float4 v = __ldcs(reinterpret_cast<const float4*>(
                W + (size_t)(d0 + r) * KDIM + (k0 + 4 * tx)));
            t[r][4 * tx + 0] = v.x;
            t[r][4 * tx + 1] = v.y;
            t[r][4 * tx + 2] = v.z;
            t[r][4 * tx + 3] = v.w;
        }
        __syncthreads();

        #pragma unroll
        for (int i = 0; i < 4; ++i) {
            int r = ty + 16 * i;
            float4 v;
            v.x = t[4 * tx + 0][r];
            v.y = t[4 * tx + 1][r];
            v.z = t[4 * tx + 2][r];
            v.w = t[4 * tx + 3][r];
            *reinterpret_cast<float4*>(
                g_Wt + (size_t)(k0 + r) * DDIM + (d0 + 4 * tx)) = v;
        }
        __syncthreads();
    }
}

// ---------------- K2: fused argmax + row gather (PDL consumer) ----------------
__global__ void __launch_bounds__(256) argmax_gather_kernel(
    const float* __restrict__ x, float* __restrict__ out)
{
    const int n   = blockIdx.x;
    const int tid = threadIdx.x;

    // ---- argmax phase: only reads x, overlaps K1 ----
    const float4* xr = reinterpret_cast<const float4*>(x + (size_t)n * KDIM);

    // front-batched loads (MLP=4 guaranteed)
    float4 v0 = __ldcs(xr + tid +   0);
    float4 v1 = __ldcs(xr + tid + 256);
    float4 v2 = __ldcs(xr + tid + 512);
    float4 v3 = __ldcs(xr + tid + 768);

    float best = -FLT_MAX;
    int   bi   = 0x7fffffff;
    {
        int b;
        b = (tid +   0) * 4;
        if (v0.x > best) { best = v0.x; bi = b + 0; }
        if (v0.y > best) { best = v0.y; bi = b + 1; }
        if (v0.z > best) { best = v0.z; bi = b + 2; }
        if (v0.w > best) { best = v0.w; bi = b + 3; }
        b = (tid + 256) * 4;
        if (v1.x > best) { best = v1.x; bi = b + 0; }
        if (v1.y > best) { best = v1.y; bi = b + 1; }
        if (v1.z > best) { best = v1.z; bi = b + 2; }
        if (v1.w > best) { best = v1.w; bi = b + 3; }
        b = (tid + 512) * 4;
        if (v2.x > best) { best = v2.x; bi = b + 0; }
        if (v2.y > best) { best = v2.y; bi = b + 1; }
        if (v2.z > best) { best = v2.z; bi = b + 2; }
        if (v2.w > best) { best = v2.w; bi = b + 3; }
        b = (tid + 768) * 4;
        if (v3.x > best) { best = v3.x; bi = b + 0; }
        if (v3.y > best) { best = v3.y; bi = b + 1; }
        if (v3.z > best) { best = v3.z; bi = b + 2; }
        if (v3.w > best) { best = v3.w; bi = b + 3; }
    }

    // warp reduce (smaller index wins ties)
    #pragma unroll
    for (int off = 16; off > 0; off >>= 1) {
        float ov = __shfl_down_sync(0xffffffffu, best, off);
        int   oi = __shfl_down_sync(0xffffffffu, bi,   off);
        if (ov > best || (ov == best && oi < bi)) { best = ov; bi = oi; }
    }

    // block reduce across 8 warps
    __shared__ float s_val[8];
    __shared__ int   s_idx[8];
    __shared__ int   s_final;
    int warp = tid >> 5;
    int lane = tid & 31;
    if (lane == 0) { s_val[warp] = best; s_idx[warp] = bi; }
    __syncthreads();
    if (warp == 0) {
        best = (lane < 8) ? s_val[lane] : -FLT_MAX;
        bi   = (lane < 8) ? s_idx[lane] : 0x7fffffff;
        #pragma unroll
        for (int off = 4; off > 0; off >>= 1) {
            float ov = __shfl_down_sync(0xffffffffu, best, off);
            int   oi = __shfl_down_sync(0xffffffffu, bi,   off);
            if (ov > best || (ov == best && oi < bi)) { best = ov; bi = oi; }
        }
        if (lane == 0) s_final = bi;
    }
    __syncthreads();
    const int idx = s_final;

    // ---- wait for K1 (transpose) completion + memory flush ----
#if __CUDA_ARCH__ >= 900
    cudaGridDependencySynchronize();
#endif

    // ---- coalesced row copy: out[n,:] = g_Wt[idx,:] ----
    const float4* src = reinterpret_cast<const float4*>(g_Wt + (size_t)idx * DDIM);
    float4*       dst = reinterpret_cast<float4*>(out + (size_t)n * DDIM);
    __stcs(dst + tid, src[tid]);
}

extern "C" void kernel_launch(void* const* d_in, const int* in_sizes, int n_in,
                              void* d_out, int out_size) {
    const float* x = (const float*)d_in[0];   // [N, K]
    const float* W = (const float*)d_in[1];   // [D, K]
    float* out = (float*)d_out;               // [N, D]

    transpose_kernel<<<TP_BLOCKS, 256>>>(W);

    cudaLaunchConfig_t cfg = {};
    cfg.gridDim  = dim3(NTOK, 1, 1);
    cfg.blockDim = dim3(256, 1, 1);
    cfg.dynamicSmemBytes = 0;
    cfg.stream = 0;
    cudaLaunchAttribute attr[1];
    attr[0].id = cudaLaunchAttributeProgrammaticStreamSerialization;
    attr[0].val.programmaticStreamSerializationAllowed = 1;
    cfg.attrs = attr;
    cfg.numAttrs = 1;
    cudaLaunchKernelEx(&cfg, argmax_gather_kernel, x, out);
}